// round 10
// baseline (speedup 1.0000x reference)
#include <cuda_runtime.h>
#include <math.h>

#define LUTN 2048
#define NEDGE 148
#define NTHR 512
#define NPREP 12
#define NTAIL 16

// ---------------- device scratch (zero-initialized at load) ----------------
__device__ float    d_binW[257], d_binWE[257];       // reset each replay by kTail
__device__ float    g_Cp[8][128], g_Dp[8][128];
__device__ float    g_uvp[4][2][128];
__device__ float    g_rsp[8][2][256];
__device__ float    g_su[129], g_uA[129], g_uB[129], g_st[257];
__device__ unsigned g_lut[LUTN];
__device__ float    g_gmax;
__device__ float    g_r[256], g_s[256];
__device__ int      g_pos[256];
__device__ float    g_Hn[256], g_S0;
__device__ float    g_Wtp[16][128];
__device__ float    g_h4p[8][256];
__device__ unsigned g_barP, g_barT;                  // monotonic barrier tickets

// wrap-safe grid barrier for small co-resident grids (nblk <= #SMs)
__device__ __forceinline__ void grid_barrier(unsigned* cnt, int nblk) {
    __syncthreads();
    if (threadIdx.x == 0) {
        __threadfence();
        unsigned t = atomicAdd(cnt, 1u);
        unsigned target = (t / nblk + 1u) * (unsigned)nblk;
        for (;;) {
            unsigned cur;
            asm volatile("ld.volatile.global.u32 %0, [%1];" : "=r"(cur) : "l"(cnt));
            if ((int)(cur - target) >= 0) break;
            __nanosleep(32);
        }
        __threadfence();
    }
    __syncthreads();
}

// ================= kPrep: distributed linearization + tables =================
__global__ __launch_bounds__(NTHR, 1)
void kPrep(const float* __restrict__ W1a, const float* __restrict__ b1a,
           const float* __restrict__ W1b, const float* __restrict__ b1b,
           const float* __restrict__ W2a, const float* __restrict__ b2a,
           const float* __restrict__ W2b, const float* __restrict__ b2b,
           const float* __restrict__ W3a, const float* __restrict__ b3a)
{
    __shared__ float s_ra[2048], s_rb[2048];           // 8KB + 8KB partial matrices
    __shared__ float s_C[128], s_D[128];
    __shared__ float s_u[128], s_v[128], s_w2b[128];
    __shared__ float s_r[256], s_s[256];
    __shared__ float s_tkey[256], s_st[257];
    __shared__ float s_ukey[128], s_su[129];
    __shared__ int   s_uord[128];
    __shared__ float s_uA[129], s_uB[129];
    __shared__ unsigned short s_lutU[LUTN], s_lutV[LUTN];
    __shared__ float s_wa[16], s_wb[16];

    int tid = threadIdx.x, bid = blockIdx.x;
    int lane = tid & 31, wid = tid >> 5;

    // -------- phase A: C/D partials (blocks 0-7, 32 j-rows each) --------
    if (bid < 8) {
        int c4 = tid & 31, jl = tid >> 5;              // 16 j-slots
        float aC[4] = {0,0,0,0}, aD[4] = {0,0,0,0};
        #pragma unroll
        for (int rep = 0; rep < 2; rep++) {
            int j = bid * 32 + jl + rep * 16;
            float a = __ldg(W1a + j), b = __ldg(b1a + j);
            float4 w = __ldg((const float4*)(W1b + j * 128) + c4);
            if (fmaf(a, 0.5f, b) > 0.f) {
                aC[0] = fmaf(a, w.x, aC[0]); aC[1] = fmaf(a, w.y, aC[1]);
                aC[2] = fmaf(a, w.z, aC[2]); aC[3] = fmaf(a, w.w, aC[3]);
                aD[0] = fmaf(b, w.x, aD[0]); aD[1] = fmaf(b, w.y, aD[1]);
                aD[2] = fmaf(b, w.z, aD[2]); aD[3] = fmaf(b, w.w, aD[3]);
            }
        }
        #pragma unroll
        for (int q = 0; q < 4; q++) {
            s_ra[jl * 128 + c4 * 4 + q] = aC[q];
            s_rb[jl * 128 + c4 * 4 + q] = aD[q];
        }
    }
    __syncthreads();
    if (bid < 8 && tid < 128) {
        float c = 0.f, d = 0.f;
        #pragma unroll
        for (int l = 0; l < 16; l++) { c += s_ra[l * 128 + tid]; d += s_rb[l * 128 + tid]; }
        g_Cp[bid][tid] = c; g_Dp[bid][tid] = d;
    }
    grid_barrier(&g_barP, NPREP);

    // -------- phase B: everyone sums C/D; compute u/v or r/s partials --------
    if (tid < 128) {
        float c = 0.f, d = 0.f;
        #pragma unroll
        for (int b = 0; b < 8; b++) { c += g_Cp[b][tid]; d += g_Dp[b][tid]; }
        s_C[tid] = c; s_D[tid] = d + __ldg(b1b + tid);
    }
    __syncthreads();
    if (bid < 4) {           // u/v partials: 32 k-rows of W2a each
        int c4 = tid & 31, kl = tid >> 5;
        float aU[4] = {0,0,0,0}, aV[4] = {0,0,0,0};
        #pragma unroll
        for (int rep = 0; rep < 2; rep++) {
            int k = bid * 32 + kl + rep * 16;
            float4 w = __ldg((const float4*)(W2a + k * 128) + c4);
            float ck = s_C[k], dk = s_D[k];
            aU[0] = fmaf(ck, w.x, aU[0]); aU[1] = fmaf(ck, w.y, aU[1]);
            aU[2] = fmaf(ck, w.z, aU[2]); aU[3] = fmaf(ck, w.w, aU[3]);
            aV[0] = fmaf(dk, w.x, aV[0]); aV[1] = fmaf(dk, w.y, aV[1]);
            aV[2] = fmaf(dk, w.z, aV[2]); aV[3] = fmaf(dk, w.w, aV[3]);
        }
        #pragma unroll
        for (int q = 0; q < 4; q++) {
            s_ra[kl * 128 + c4 * 4 + q] = aU[q];
            s_rb[kl * 128 + c4 * 4 + q] = aV[q];
        }
        __syncthreads();
        if (tid < 128) {
            float u = 0.f, v = 0.f;
            #pragma unroll
            for (int l = 0; l < 16; l++) { u += s_ra[l * 128 + tid]; v += s_rb[l * 128 + tid]; }
            g_uvp[bid][0][tid] = u; g_uvp[bid][1][tid] = v;
        }
    } else {                 // blocks 4-11: r/s partials: 32 k-rows of W3a each
        int kb = bid - 4;
        int c4 = tid & 63, kl = tid >> 6;              // 8 k-slots
        float aR[4] = {0,0,0,0}, aS[4] = {0,0,0,0};
        #pragma unroll
        for (int rep = 0; rep < 4; rep++) {
            int k = kb * 32 + kl + rep * 8;
            float4 w = __ldg((const float4*)(W3a + k * 256) + c4);
            float ck = s_C[k], dk = s_D[k];
            aR[0] = fmaf(ck, w.x, aR[0]); aR[1] = fmaf(ck, w.y, aR[1]);
            aR[2] = fmaf(ck, w.z, aR[2]); aR[3] = fmaf(ck, w.w, aR[3]);
            aS[0] = fmaf(dk, w.x, aS[0]); aS[1] = fmaf(dk, w.y, aS[1]);
            aS[2] = fmaf(dk, w.z, aS[2]); aS[3] = fmaf(dk, w.w, aS[3]);
        }
        #pragma unroll
        for (int q = 0; q < 4; q++) {
            s_ra[kl * 256 + c4 * 4 + q] = aR[q];
            s_rb[kl * 256 + c4 * 4 + q] = aS[q];
        }
        __syncthreads();
        if (tid < 256) {
            float r = 0.f, sv = 0.f;
            #pragma unroll
            for (int l = 0; l < 8; l++) { r += s_ra[l * 256 + tid]; sv += s_rb[l * 256 + tid]; }
            g_rsp[kb][0][tid] = r; g_rsp[kb][1][tid] = sv;
        }
    }
    grid_barrier(&g_barP, NPREP);

    // -------- phase C: block 0 builds tiny tables --------
    if (bid != 0) return;
    if (tid < 128) {
        float u = 0.f, v = 0.f;
        #pragma unroll
        for (int b = 0; b < 4; b++) { u += g_uvp[b][0][tid]; v += g_uvp[b][1][tid]; }
        s_u[tid] = u; s_v[tid] = v + __ldg(b2a + tid);
        s_w2b[tid] = __ldg(W2b + tid);
    }
    if (tid < 256) {
        float r = 0.f, sv = 0.f;
        #pragma unroll
        for (int b = 0; b < 8; b++) { r += g_rsp[b][0][tid]; sv += g_rsp[b][1][tid]; }
        sv += __ldg(b3a + tid);
        s_r[tid] = r; s_s[tid] = sv;
        g_r[tid] = r; g_s[tid] = sv;
        float key = 1.0f;
        if (r != 0.f) key = fminf(fmaxf(-sv / r, 0.f), 1.f);
        s_tkey[tid] = key;
    }
    __syncthreads();
    if (tid < 128) {
        float uu = s_u[tid], vv = s_v[tid], key = 2.f;
        if (uu != 0.f) { float t = -vv / uu; if (t > 0.f && t < 1.f) key = t; }
        s_ukey[tid] = key;
    }
    __syncthreads();
    // rank-by-counting, disjoint warp sets
    if (tid < 256) {
        float key = s_tkey[tid]; int rank = 0;
        #pragma unroll 16
        for (int j = 0; j < 256; j++) {
            float kj = s_tkey[j];
            rank += (kj < key) || (kj == key && j < tid);
        }
        s_st[rank] = key;
        g_pos[tid] = rank + 1;
    } else if (tid < 384) {
        int k = tid - 256;
        float key = s_ukey[k]; int rank = 0;
        #pragma unroll 16
        for (int j = 0; j < 128; j++) {
            float kj = s_ukey[j];
            rank += (kj < key) || (kj == key && j < k);
        }
        s_su[rank] = key; s_uord[rank] = k;
    }
    if (tid == 0) { s_st[256] = 2.f; s_su[128] = 2.f; }
    for (int b = tid; b < LUTN; b += NTHR) { s_lutU[b] = 0; s_lutV[b] = 0; }
    __syncthreads();
    // LUT scatter fill
    {
        int k = tid >> 2, g = tid & 3;
        float k0 = s_su[k], k1 = s_su[k + 1];
        int st_ = min((int)ceilf(k0 * (float)LUTN), LUTN);
        int en  = min((int)ceilf(k1 * (float)LUTN), LUTN);
        for (int b = st_ + g; b < en; b += 4) s_lutU[b] = (unsigned short)(k + 1);
    }
    {
        int k = tid >> 1, g = tid & 1;
        float k0 = s_st[k], k1 = s_st[k + 1];
        int st_ = min((int)ceilf(k0 * (float)LUTN), LUTN);
        int en  = min((int)ceilf(k1 * (float)LUTN), LUTN);
        for (int b = st_ + g; b < en; b += 2) s_lutV[b] = (unsigned short)(k + 1);
    }
    // A0/B0 at midpoint of first segment
    float em0 = 0.5f * fminf(s_su[0], 1.f);
    {
        float a0 = 0.f, b0 = 0.f;
        if (tid < 128 && fmaf(s_u[tid], em0, s_v[tid]) > 0.f) {
            a0 = s_u[tid] * s_w2b[tid]; b0 = s_v[tid] * s_w2b[tid];
        }
        #pragma unroll
        for (int o = 16; o > 0; o >>= 1) {
            a0 += __shfl_xor_sync(~0u, a0, o);
            b0 += __shfl_xor_sync(~0u, b0, o);
        }
        if (lane == 0) { s_wa[wid] = a0; s_wb[wid] = b0; }
    }
    __syncthreads();
    float A0 = s_wa[0] + s_wa[1] + s_wa[2] + s_wa[3];
    float B0 = s_wb[0] + s_wb[1] + s_wb[2] + s_wb[3] + __ldg(b2b);
    __syncthreads();
    {   // inclusive shuffle scan of flip deltas
        float dA = 0.f, dB = 0.f;
        if (tid < 128) {
            float key = s_su[tid];
            if (key < 1.f) {
                int i = s_uord[tid];
                float sg = (s_u[i] > 0.f) ? 1.f : -1.f;
                dA = sg * s_u[i] * s_w2b[i];
                dB = sg * s_v[i] * s_w2b[i];
            }
        }
        float ia = dA, ib = dB;
        #pragma unroll
        for (int o = 1; o < 32; o <<= 1) {
            float ta = __shfl_up_sync(~0u, ia, o), tb = __shfl_up_sync(~0u, ib, o);
            if (lane >= o) { ia += ta; ib += tb; }
        }
        if (tid < 128 && lane == 31) { s_wa[8 + wid] = ia; s_wb[8 + wid] = ib; }
        __syncthreads();
        if (tid < 128) {
            float oa = 0.f, ob = 0.f;
            for (int w = 0; w < wid; w++) { oa += s_wa[8 + w]; ob += s_wb[8 + w]; }
            s_uA[tid + 1] = A0 + ia + oa;
            s_uB[tid + 1] = B0 + ib + ob;
        }
        if (tid == 0) { s_uA[0] = A0; s_uB[0] = B0; }
    }
    __syncthreads();
    {   // gmax over segment endpoints
        float gm = -3.0e38f;
        if (tid <= 128) {
            float lo = tid ? fminf(s_su[tid - 1], 1.f) : 0.f;
            float hi = (tid < 128) ? fminf(s_su[tid], 1.f) : 1.f;
            gm = fmaxf(fmaf(s_uA[tid], lo, s_uB[tid]), fmaf(s_uA[tid], hi, s_uB[tid]));
        }
        #pragma unroll
        for (int o = 16; o > 0; o >>= 1) gm = fmaxf(gm, __shfl_xor_sync(~0u, gm, o));
        if (lane == 0) s_wa[wid] = gm;
        __syncthreads();
        if (tid == 0) {
            float g = s_wa[0];
            #pragma unroll
            for (int w = 1; w < 16; w++) g = fmaxf(g, s_wa[w]);
            g_gmax = g;
        }
    }
    __syncthreads();
    // publish tables
    if (tid < 129) { g_su[tid] = s_su[tid]; g_uA[tid] = s_uA[tid]; g_uB[tid] = s_uB[tid]; }
    if (tid < 257) g_st[tid] = s_st[tid];
    for (int b = tid; b < LUTN; b += NTHR)
        g_lut[b] = ((unsigned)s_lutU[b] << 16) | (unsigned)s_lutV[b];
}

// ================= kEdge: O(1)/edge pass + bin flush =================
__global__ __launch_bounds__(NTHR, 1)
void kEdge(const float* __restrict__ adj, int P)
{
    __shared__ unsigned s_lut[LUTN];
    __shared__ float s_su[129], s_uA[129], s_uB[129];
    __shared__ float s_st[257];
    __shared__ float s_binW[257], s_binWE[257];

    int tid = threadIdx.x, bid = blockIdx.x;
    for (int b = tid; b < LUTN; b += NTHR) s_lut[b] = __ldg(&g_lut[b]);
    if (tid < 129) { s_su[tid] = g_su[tid]; s_uA[tid] = g_uA[tid]; s_uB[tid] = g_uB[tid]; }
    if (tid < 257) { s_st[tid] = g_st[tid]; s_binW[tid] = 0.f; s_binWE[tid] = 0.f; }
    __syncthreads();
    float gmax = g_gmax;

    int nq = P >> 2;
    const float4* a4 = (const float4*)adj;
    for (int q = bid * NTHR + tid; q < nq; q += NEDGE * NTHR) {
        float4 v = __ldg(a4 + q);
        float es[4] = {v.x, v.y, v.z, v.w};
        #pragma unroll
        for (int j = 0; j < 4; j++) {
            float e = es[j];
            if (e > 0.f && e < 1.f) {
                unsigned lv = s_lut[(int)(e * (float)LUTN)];
                int useg = lv >> 16, vbin = lv & 0xffff;
                while (useg < 128 && s_su[useg] <= e) useg++;
                while (vbin < 256 && s_st[vbin] <= e) vbin++;
                float w = __expf(fmaf(s_uA[useg], e, s_uB[useg]) - gmax);
                atomicAdd(&s_binW[vbin], w);
                atomicAdd(&s_binWE[vbin], w * e);
            }
        }
    }
    for (int pp = (nq << 2) + bid * NTHR + tid; pp < P; pp += NEDGE * NTHR) {
        float e = __ldg(adj + pp);
        if (e > 0.f && e < 1.f) {
            unsigned lv = s_lut[(int)(e * (float)LUTN)];
            int useg = lv >> 16, vbin = lv & 0xffff;
            while (useg < 128 && s_su[useg] <= e) useg++;
            while (vbin < 256 && s_st[vbin] <= e) vbin++;
            float w = __expf(fmaf(s_uA[useg], e, s_uB[useg]) - gmax);
            atomicAdd(&s_binW[vbin], w);
            atomicAdd(&s_binWE[vbin], w * e);
        }
    }
    __syncthreads();
    if (tid < 257) {
        float w = s_binW[tid], we = s_binWE[tid];
        if (w != 0.f || we != 0.f) {
            atomicAdd(&d_binW[tid], w);
            atomicAdd(&d_binWE[tid], we);
        }
    }
}

// ================= kTail: scan -> Hn -> distributed head MLP =================
__global__ __launch_bounds__(NTHR, 1)
void kTail(const float* __restrict__ W3b, const float* __restrict__ b3b,
           const float* __restrict__ W4a, const float* __restrict__ b4a,
           const float* __restrict__ W4b, const float* __restrict__ b4b,
           float* __restrict__ out)
{
    __shared__ float s_PF[257], s_PG[257];
    __shared__ float s_wa[16], s_wb[16];
    __shared__ float s_Hn[256];
    __shared__ float s_m[16 * 128];       // 8KB reduce buffer (Wt + h4 phases)
    __shared__ float s_Wt[128], s_H4[256];
    __shared__ float s_red[NTHR];

    int tid = threadIdx.x, bid = blockIdx.x;
    int lane = tid & 31, wid = tid >> 5;

    // -------- phase 0: block 0 scans bins, computes Hn, resets bins --------
    if (bid == 0) {
        float binw = 0.f, binwe = 0.f;
        if (tid < 257) {
            binw = d_binW[tid]; binwe = d_binWE[tid];
            d_binW[tid] = 0.f; d_binWE[tid] = 0.f;
        }
        float ia = binw, ib = binwe;
        #pragma unroll
        for (int o = 1; o < 32; o <<= 1) {
            float ta = __shfl_up_sync(~0u, ia, o), tb = __shfl_up_sync(~0u, ib, o);
            if (lane >= o) { ia += ta; ib += tb; }
        }
        if (lane == 31 && wid < 9) { s_wa[wid] = ia; s_wb[wid] = ib; }
        __syncthreads();
        if (tid < 257) {
            float oa = 0.f, ob = 0.f;
            for (int w = 0; w < wid; w++) { oa += s_wa[w]; ob += s_wb[w]; }
            s_PF[tid] = ia + oa; s_PG[tid] = ib + ob;
        }
        __syncthreads();
        float Z = s_PF[256], Gtot = s_PG[256];
        float invZ = (Z > 0.f) ? (1.f / Z) : 0.f;
        if (tid == 0) g_S0 = (Z > 0.f) ? 1.f : 0.f;
        if (tid < 256) {
            float r = __ldg(&g_r[tid]), s = __ldg(&g_s[tid]);
            int m = __ldg(&g_pos[tid]);
            float H;
            if (r > 0.f)      H = r * (Gtot - s_PG[m - 1]) + s * (Z - s_PF[m - 1]);
            else if (r < 0.f) H = r * s_PG[m - 1] + s * s_PF[m - 1];
            else              H = (s > 0.f) ? s * Z : 0.f;
            g_Hn[tid] = H * invZ;
        }
    }
    grid_barrier(&g_barT, NTAIL);

    // -------- phase 1: Wt partials (16 blocks x 16 d-rows of W3b) --------
    if (tid < 256) s_Hn[tid] = g_Hn[tid];
    __syncthreads();
    {
        int j4 = tid & 31, dl = tid >> 5;              // 16 d-slots, 1 float4 each
        int d = bid * 16 + dl;
        float4 w = __ldg((const float4*)(W3b + d * 128) + j4);
        float h = s_Hn[d];
        s_m[dl * 128 + j4 * 4 + 0] = h * w.x;
        s_m[dl * 128 + j4 * 4 + 1] = h * w.y;
        s_m[dl * 128 + j4 * 4 + 2] = h * w.z;
        s_m[dl * 128 + j4 * 4 + 3] = h * w.w;
    }
    __syncthreads();
    if (tid < 128) {
        float p = 0.f;
        #pragma unroll
        for (int l = 0; l < 16; l++) p += s_m[l * 128 + tid];
        g_Wtp[bid][tid] = p;
    }
    grid_barrier(&g_barT, NTAIL);

    // -------- phase 2: h4 partials (blocks 0-7 x 16 m-rows of W4a) --------
    if (bid < 8) {
        if (tid < 128) {
            float wt = 0.f;
            #pragma unroll
            for (int b = 0; b < 16; b++) wt += g_Wtp[b][tid];
            s_Wt[tid] = wt + g_S0 * __ldg(b3b + tid);
        }
        __syncthreads();
        int c4 = tid & 63, ml = tid >> 6;              // 8 m-slots
        float a4[4] = {0,0,0,0};
        #pragma unroll
        for (int rep = 0; rep < 2; rep++) {
            int m = bid * 16 + ml + rep * 8;
            float4 w = __ldg((const float4*)(W4a + m * 256) + c4);
            float wm = s_Wt[m];
            a4[0] = fmaf(wm, w.x, a4[0]); a4[1] = fmaf(wm, w.y, a4[1]);
            a4[2] = fmaf(wm, w.z, a4[2]); a4[3] = fmaf(wm, w.w, a4[3]);
        }
        #pragma unroll
        for (int q = 0; q < 4; q++) s_m[ml * 256 + c4 * 4 + q] = a4[q];
        __syncthreads();
        if (tid < 256) {
            float p = 0.f;
            #pragma unroll
            for (int l = 0; l < 8; l++) p += s_m[l * 256 + tid];
            g_h4p[bid][tid] = p;
        }
    }
    grid_barrier(&g_barT, NTAIL);

    // -------- phase 3: block 0 final (W4b only, 64KB) --------
    if (bid != 0) return;
    if (tid < 256) {
        float h = 0.f;
        #pragma unroll
        for (int b = 0; b < 8; b++) h += g_h4p[b][tid];
        s_H4[tid] = fmaxf(h + __ldg(b4a + tid), 0.f);
    }
    __syncthreads();
    {
        int o = tid & 63, team = tid >> 6;             // 8 teams x 32 n
        float acc = 0.f;
        int n0 = team * 32;
        #pragma unroll 8
        for (int n = n0; n < n0 + 32; n++)
            acc = fmaf(s_H4[n], __ldg(W4b + n * 64 + o), acc);
        s_red[tid] = acc;
    }
    __syncthreads();
    if (tid < 64) {
        float o = __ldg(b4b + tid);
        #pragma unroll
        for (int q = 0; q < 8; q++) o += s_red[q * 64 + tid];
        out[tid] = o;
    }
}

// ---------------- launch: 3 graph nodes ----------------
extern "C" void kernel_launch(void* const* d_in, const int* in_sizes, int n_in,
                              void* d_out, int out_size) {
    const float* adj = (const float*)d_in[1];
    int P = in_sizes[1];
    kPrep<<<NPREP, NTHR>>>(
        (const float*)d_in[3],  (const float*)d_in[4],
        (const float*)d_in[5],  (const float*)d_in[6],
        (const float*)d_in[7],  (const float*)d_in[8],
        (const float*)d_in[9],  (const float*)d_in[10],
        (const float*)d_in[11], (const float*)d_in[12]);
    kEdge<<<NEDGE, NTHR>>>(adj, P);
    kTail<<<NTAIL, NTHR>>>(
        (const float*)d_in[13], (const float*)d_in[14],
        (const float*)d_in[15], (const float*)d_in[16],
        (const float*)d_in[17], (const float*)d_in[18],
        (float*)d_out);
}

// round 14
// speedup vs baseline: 1.0304x; 1.0304x over previous
#include <cuda_runtime.h>
#include <math.h>

#define LUTN  1024
#define NGRID 140
#define NTHR  512

// ---------------- device scratch (zero-initialized at load) ----------------
__device__ float    d_binW[257], d_binWE[257];   // cycle 0 -> full -> 0 each launch
__device__ float    g_outAcc[64];                // atomic out partials, reset by block 0
__device__ float    g_gsu[129], g_guA[129], g_guB[129], g_gst[257];
__device__ unsigned g_glut[LUTN];
__device__ float    g_gmaxv;
__device__ float    g_rr[256], g_ss[256];
__device__ int      g_pos[256];
__device__ unsigned g_epoch, g_tab, g_flush, g_tail;

// R6-proven idioms: ALL threads fence, then sync, then tid0 tickets.
__device__ __forceinline__ void sigall(unsigned* c) {
    __threadfence();
    __syncthreads();
    if (threadIdx.x == 0) atomicAdd(c, 1u);
}
__device__ __forceinline__ void waitge(unsigned* c, unsigned target) {
    if (threadIdx.x == 0) {
        for (;;) {
            unsigned cur;
            asm volatile("ld.volatile.global.u32 %0, [%1];" : "=r"(cur) : "l"(c) : "memory");
            if ((int)(cur - target) >= 0) break;
            __nanosleep(64);
        }
        __threadfence();
    }
    __syncthreads();
}

__global__ __launch_bounds__(NTHR, 1)
void kAll(const float* __restrict__ adj, int P,
          const float* __restrict__ W1a, const float* __restrict__ b1a,
          const float* __restrict__ W1b, const float* __restrict__ b1b,
          const float* __restrict__ W2a, const float* __restrict__ b2a,
          const float* __restrict__ W2b, const float* __restrict__ b2b,
          const float* __restrict__ W3a, const float* __restrict__ b3a,
          const float* __restrict__ W3b, const float* __restrict__ b3b,
          const float* __restrict__ W4a, const float* __restrict__ b4a,
          const float* __restrict__ W4b, const float* __restrict__ b4b,
          float* __restrict__ out)
{
    __shared__ float s_W1a[256], s_B1a[256];
    __shared__ float s_pa[4][128], s_pb[4][128];
    __shared__ float s_pr[2][256], s_ps[2][256];
    __shared__ float s_C[128], s_D[128];
    __shared__ float s_cu[128], s_cv[128], s_cw2b[128];
    __shared__ float s_ctk[256], s_cuk[128];
    __shared__ int   s_cuo[128];
    __shared__ unsigned short s_lutU[LUTN], s_lutV[LUTN];
    __shared__ float s_su[129], s_uA[129], s_uB[129];
    __shared__ float s_st[257];
    __shared__ unsigned s_lut[LUTN];
    __shared__ float s_bW[257], s_bWE[257];
    __shared__ float s_wa[16], s_wb[16];
    __shared__ float s_PF[257], s_PG[257];
    __shared__ float s_Hn[256], s_Wt[128], s_h4[64];
    __shared__ float s_red[NTHR];
    __shared__ unsigned s_ep;

    int tid = threadIdx.x, bid = blockIdx.x;
    int lane = tid & 31, wid = tid >> 5;
    int col = tid & 127, team = tid >> 7;      // 4 teams of 128
    int col2 = tid & 255, team2 = tid >> 8;    // 2 teams of 256

    if (tid == 0) s_ep = atomicAdd(&g_epoch, 1u) / NGRID;
    __syncthreads();
    unsigned ep = s_ep;

    // ---------- adj register preload: covers ALL edges (overlaps setup) ----------
    const float4* a4 = (const float4*)adj;
    int nq = P >> 2;
    int stride = NGRID * NTHR;
    int q0 = bid * NTHR + tid, q1 = q0 + stride;
    float4 e0 = make_float4(2.f,2.f,2.f,2.f), e1 = make_float4(2.f,2.f,2.f,2.f);
    if (q0 < nq) e0 = __ldg(a4 + q0);
    if (q1 < nq) e1 = __ldg(a4 + q1);

    // ================= block 0: solo table construction (proven R8/R9 code) =================
    if (bid == 0) {
        if (tid < 256) { s_W1a[tid] = W1a[tid]; s_B1a[tid] = b1a[tid]; }
        __syncthreads();
        {   // C/D: 4 teams x 64 j-rows of W1b
            float c = 0.f, d = 0.f; int j0 = team * 64;
            #pragma unroll 16
            for (int j = j0; j < j0 + 64; j++) {
                float a = s_W1a[j], b = s_B1a[j];
                float w = __ldg(W1b + j * 128 + col);
                if (fmaf(a, 0.5f, b) > 0.f) { c = fmaf(a, w, c); d = fmaf(b, w, d); }
            }
            s_pa[team][col] = c; s_pb[team][col] = d;
        }
        __syncthreads();
        if (tid < 128) {
            s_C[tid] = s_pa[0][tid] + s_pa[1][tid] + s_pa[2][tid] + s_pa[3][tid];
            s_D[tid] = s_pb[0][tid] + s_pb[1][tid] + s_pb[2][tid] + s_pb[3][tid] + __ldg(b1b + tid);
        }
        __syncthreads();
        {   // u/v: 4 teams x 32 k-rows of W2a
            float uu = 0.f, vv = 0.f; int k0 = team * 32;
            #pragma unroll
            for (int k = k0; k < k0 + 32; k++) {
                float w = __ldg(W2a + k * 128 + col);
                uu = fmaf(s_C[k], w, uu); vv = fmaf(s_D[k], w, vv);
            }
            s_pa[team][col] = uu; s_pb[team][col] = vv;
        }
        {   // r/s: 2 teams x 64 k-rows of W3a
            float r = 0.f, sv = 0.f; int k0 = team2 * 64;
            #pragma unroll 8
            for (int k = k0; k < k0 + 64; k++) {
                float w = __ldg(W3a + k * 256 + col2);
                r = fmaf(s_C[k], w, r); sv = fmaf(s_D[k], w, sv);
            }
            s_pr[team2][col2] = r; s_ps[team2][col2] = sv;
        }
        __syncthreads();
        if (tid < 128) {
            s_cu[tid] = s_pa[0][tid] + s_pa[1][tid] + s_pa[2][tid] + s_pa[3][tid];
            s_cv[tid] = s_pb[0][tid] + s_pb[1][tid] + s_pb[2][tid] + s_pb[3][tid] + __ldg(b2a + tid);
            s_cw2b[tid] = __ldg(W2b + tid);
        }
        if (tid < 256) {
            float r = s_pr[0][tid] + s_pr[1][tid];
            float sv = s_ps[0][tid] + s_ps[1][tid] + __ldg(b3a + tid);
            g_rr[tid] = r; g_ss[tid] = sv;                    // publish (plain stores)
            float key = 1.0f;
            if (r != 0.f) key = fminf(fmaxf(-sv / r, 0.f), 1.f);
            s_ctk[tid] = key;
        }
        __syncthreads();
        if (tid < 128) {
            float uu = s_cu[tid], vv = s_cv[tid], key = 2.f;
            if (uu != 0.f) { float t = -vv / uu; if (t > 0.f && t < 1.f) key = t; }
            s_cuk[tid] = key;
        }
        __syncthreads();
        // rank-by-counting, disjoint warp sets
        if (tid < 256) {
            float key = s_ctk[tid]; int rank = 0;
            #pragma unroll 16
            for (int j = 0; j < 256; j++) {
                float kj = s_ctk[j];
                rank += (kj < key) || (kj == key && j < tid);
            }
            s_st[rank] = key;
            g_pos[tid] = rank + 1;
        } else if (tid < 384) {
            int k = tid - 256;
            float key = s_cuk[k]; int rank = 0;
            #pragma unroll 16
            for (int j = 0; j < 128; j++) {
                float kj = s_cuk[j];
                rank += (kj < key) || (kj == key && j < k);
            }
            s_su[rank] = key; s_cuo[rank] = k;
        }
        if (tid == 0) { s_st[256] = 2.f; s_su[128] = 2.f; }
        for (int b = tid; b < LUTN; b += NTHR) { s_lutU[b] = 0; s_lutV[b] = 0; }
        __syncthreads();
        // LUT scatter fill (LUTN power of 2 -> key*LUTN exact)
        {
            int k = tid >> 2, g = tid & 3;                    // k in 0..127
            float k0 = s_su[k], k1 = s_su[k + 1];
            int st_ = min((int)ceilf(k0 * (float)LUTN), LUTN);
            int en  = min((int)ceilf(k1 * (float)LUTN), LUTN);
            for (int b = st_ + g; b < en; b += 4) s_lutU[b] = (unsigned short)(k + 1);
        }
        {
            int k = tid >> 1, g = tid & 1;                    // k in 0..255
            float k0 = s_st[k], k1 = s_st[k + 1];
            int st_ = min((int)ceilf(k0 * (float)LUTN), LUTN);
            int en  = min((int)ceilf(k1 * (float)LUTN), LUTN);
            for (int b = st_ + g; b < en; b += 2) s_lutV[b] = (unsigned short)(k + 1);
        }
        // A0/B0 at midpoint of first u-segment
        float em0 = 0.5f * fminf(s_su[0], 1.f);
        {
            float a0 = 0.f, b0 = 0.f;
            if (tid < 128 && fmaf(s_cu[tid], em0, s_cv[tid]) > 0.f) {
                a0 = s_cu[tid] * s_cw2b[tid]; b0 = s_cv[tid] * s_cw2b[tid];
            }
            #pragma unroll
            for (int o = 16; o > 0; o >>= 1) {
                a0 += __shfl_xor_sync(~0u, a0, o);
                b0 += __shfl_xor_sync(~0u, b0, o);
            }
            if (lane == 0) { s_wa[wid] = a0; s_wb[wid] = b0; }
        }
        __syncthreads();
        float A0 = s_wa[0] + s_wa[1] + s_wa[2] + s_wa[3];
        float B0 = s_wb[0] + s_wb[1] + s_wb[2] + s_wb[3] + __ldg(b2b);
        __syncthreads();
        {   // inclusive shuffle scan of flip deltas over sorted u-slots
            float dA = 0.f, dB = 0.f;
            if (tid < 128) {
                float key = s_su[tid];
                if (key < 1.f) {
                    int i = s_cuo[tid];
                    float sg = (s_cu[i] > 0.f) ? 1.f : -1.f;
                    dA = sg * s_cu[i] * s_cw2b[i];
                    dB = sg * s_cv[i] * s_cw2b[i];
                }
            }
            float ia = dA, ib = dB;
            #pragma unroll
            for (int o = 1; o < 32; o <<= 1) {
                float ta = __shfl_up_sync(~0u, ia, o), tb = __shfl_up_sync(~0u, ib, o);
                if (lane >= o) { ia += ta; ib += tb; }
            }
            if (tid < 128 && lane == 31) { s_wa[8 + wid] = ia; s_wb[8 + wid] = ib; }
            __syncthreads();
            if (tid < 128) {
                float oa = 0.f, ob = 0.f;
                for (int w = 0; w < wid; w++) { oa += s_wa[8 + w]; ob += s_wb[8 + w]; }
                s_uA[tid + 1] = A0 + ia + oa;
                s_uB[tid + 1] = B0 + ib + ob;
            }
            if (tid == 0) { s_uA[0] = A0; s_uB[0] = B0; }
        }
        __syncthreads();
        {   // gmax over segment endpoints
            float gm = -3.0e38f;
            if (tid <= 128) {
                float lo = tid ? fminf(s_su[tid - 1], 1.f) : 0.f;
                float hi = (tid < 128) ? fminf(s_su[tid], 1.f) : 1.f;
                gm = fmaxf(fmaf(s_uA[tid], lo, s_uB[tid]), fmaf(s_uA[tid], hi, s_uB[tid]));
            }
            #pragma unroll
            for (int o = 16; o > 0; o >>= 1) gm = fmaxf(gm, __shfl_xor_sync(~0u, gm, o));
            if (lane == 0) s_wa[wid] = gm;
            __syncthreads();
            if (tid == 0) {
                float g = s_wa[0];
                #pragma unroll
                for (int w = 1; w < 16; w++) g = fmaxf(g, s_wa[w]);
                g_gmaxv = g;
            }
        }
        __syncthreads();
        // publish tables (plain stores), then R6-idiom ticket
        if (tid < 129) { g_gsu[tid] = s_su[tid]; g_guA[tid] = s_uA[tid]; g_guB[tid] = s_uB[tid]; }
        if (tid < 257) g_gst[tid] = s_st[tid];
        for (int b = tid; b < LUTN; b += NTHR)
            g_glut[b] = ((unsigned)s_lutU[b] << 16) | (unsigned)s_lutV[b];
        sigall(&g_tab);
    }

    // ================= gate: tables ready (one-way; block 0 passes instantly) =================
    waitge(&g_tab, ep + 1u);
    s_lut[tid] = g_glut[tid];                       // plain loads (NOT __ldg: same-launch data)
    s_lut[tid + 512] = g_glut[tid + 512];
    if (tid < 129) { s_su[tid] = g_gsu[tid]; s_uA[tid] = g_guA[tid]; s_uB[tid] = g_guB[tid]; }
    if (tid < 257) { s_st[tid] = g_gst[tid]; s_bW[tid] = 0.f; s_bWE[tid] = 0.f; }
    __syncthreads();
    float gmax = g_gmaxv;

    // ================= edge pass (registers; leftovers via generic loops) =================
    {
        float es[8] = {e0.x, e0.y, e0.z, e0.w, e1.x, e1.y, e1.z, e1.w};
        #pragma unroll
        for (int j = 0; j < 8; j++) {
            float e = es[j];
            if (e > 0.f && e < 1.f) {               // preload pads (2.0) skipped
                unsigned lv = s_lut[min((int)(e * (float)LUTN), LUTN - 1)];
                int useg = min((int)(lv >> 16), 128), vbin = min((int)(lv & 0xffffu), 256);
                while (useg < 128 && s_su[useg] <= e) useg++;
                while (vbin < 256 && s_st[vbin] <= e) vbin++;
                float w = __expf(fmaf(s_uA[useg], e, s_uB[useg]) - gmax);
                atomicAdd(&s_bW[vbin], w);
                atomicAdd(&s_bWE[vbin], w * e);
            }
        }
        for (int q = q0 + 2 * stride; q < nq; q += stride) {
            float4 v = __ldg(a4 + q);
            float ee[4] = {v.x, v.y, v.z, v.w};
            #pragma unroll
            for (int j = 0; j < 4; j++) {
                float e = ee[j];
                if (e > 0.f && e < 1.f) {
                    unsigned lv = s_lut[min((int)(e * (float)LUTN), LUTN - 1)];
                    int useg = min((int)(lv >> 16), 128), vbin = min((int)(lv & 0xffffu), 256);
                    while (useg < 128 && s_su[useg] <= e) useg++;
                    while (vbin < 256 && s_st[vbin] <= e) vbin++;
                    float w = __expf(fmaf(s_uA[useg], e, s_uB[useg]) - gmax);
                    atomicAdd(&s_bW[vbin], w);
                    atomicAdd(&s_bWE[vbin], w * e);
                }
            }
        }
        for (int pp = (nq << 2) + bid * NTHR + tid; pp < P; pp += stride) {
            float e = __ldg(adj + pp);
            if (e > 0.f && e < 1.f) {
                unsigned lv = s_lut[min((int)(e * (float)LUTN), LUTN - 1)];
                int useg = min((int)(lv >> 16), 128), vbin = min((int)(lv & 0xffffu), 256);
                while (useg < 128 && s_su[useg] <= e) useg++;
                while (vbin < 256 && s_st[vbin] <= e) vbin++;
                float w = __expf(fmaf(s_uA[useg], e, s_uB[useg]) - gmax);
                atomicAdd(&s_bW[vbin], w);
                atomicAdd(&s_bWE[vbin], w * e);
            }
        }
    }
    __syncthreads();
    if (tid < 257) {
        float w = s_bW[tid], we = s_bWE[tid];
        if (w != 0.f || we != 0.f) {
            atomicAdd(&d_binW[tid], w);
            atomicAdd(&d_binWE[tid], we);
        }
    }
    sigall(&g_flush);
    if (bid >= 4) return;                            // producers never wait past here

    // ================= tail: 4 waiter blocks =================
    waitge(&g_flush, (ep + 1u) * (unsigned)NGRID);

    // scan over 257 bins (redundant per waiter; plain loads)
    {
        float binw = 0.f, binwe = 0.f;
        if (tid < 257) { binw = d_binW[tid]; binwe = d_binWE[tid]; }
        float ia = binw, ib = binwe;
        #pragma unroll
        for (int o = 1; o < 32; o <<= 1) {
            float ta = __shfl_up_sync(~0u, ia, o), tb = __shfl_up_sync(~0u, ib, o);
            if (lane >= o) { ia += ta; ib += tb; }
        }
        if (lane == 31 && wid < 9) { s_wa[wid] = ia; s_wb[wid] = ib; }
        __syncthreads();
        if (tid < 257) {
            float oa = 0.f, ob = 0.f;
            for (int w = 0; w < wid; w++) { oa += s_wa[w]; ob += s_wb[w]; }
            s_PF[tid] = ia + oa; s_PG[tid] = ib + ob;
        }
    }
    __syncthreads();
    float Z = s_PF[256], Gtot = s_PG[256];
    float invZ = (Z > 0.f) ? (1.f / Z) : 0.f;
    float S0   = (Z > 0.f) ? 1.f : 0.f;

    // Hn per dim (plain loads of same-launch tables)
    if (tid < 256) {
        float r = g_rr[tid], s = g_ss[tid];
        int m = g_pos[tid];
        float H;
        if (r > 0.f)      H = r * (Gtot - s_PG[m - 1]) + s * (Z - s_PF[m - 1]);
        else if (r < 0.f) H = r * s_PG[m - 1] + s * s_PF[m - 1];
        else              H = (s > 0.f) ? s * Z : 0.f;
        s_Hn[tid] = H * invZ;
    }
    __syncthreads();

    // full Wt per waiter (4 teams x 64 d-rows of W3b; weights const -> __ldg fine)
    {
        float a2 = 0.f; int d0 = team * 64;
        #pragma unroll 8
        for (int d = d0; d < d0 + 64; d++)
            a2 = fmaf(s_Hn[d], __ldg(W3b + d * 128 + col), a2);
        s_pa[team][col] = a2;
    }
    __syncthreads();
    if (tid < 128)
        s_Wt[tid] = s_pa[0][tid] + s_pa[1][tid] + s_pa[2][tid] + s_pa[3][tid] + S0 * __ldg(b3b + tid);
    __syncthreads();

    // h4 slice: n in [bid*64, bid*64+64)
    {
        int o = tid & 63, g8 = tid >> 6;             // 8 groups x 16 m-rows
        float p = 0.f; int m0 = g8 * 16;
        #pragma unroll
        for (int m = m0; m < m0 + 16; m++)
            p = fmaf(s_Wt[m], __ldg(W4a + m * 256 + bid * 64 + o), p);
        s_red[g8 * 64 + o] = p;
    }
    __syncthreads();
    if (tid < 64) {
        float h = __ldg(b4a + bid * 64 + tid);
        #pragma unroll
        for (int g8 = 0; g8 < 8; g8++) h += s_red[g8 * 64 + tid];
        s_h4[tid] = fmaxf(h, 0.f);
    }
    __syncthreads();

    // out partials over this waiter's 64 n-rows of W4b -> atomic accumulator
    {
        int o = tid & 63, g8 = tid >> 6;             // 8 groups x 8 n-rows
        float p = 0.f;
        #pragma unroll
        for (int q = 0; q < 8; q++) {
            int nl = g8 * 8 + q;
            p = fmaf(s_h4[nl], __ldg(W4b + (bid * 64 + nl) * 64 + o), p);
        }
        s_red[g8 * 64 + o] = p;
    }
    __syncthreads();
    if (tid < 64) {
        float p = 0.f;
        #pragma unroll
        for (int g8 = 0; g8 < 8; g8++) p += s_red[g8 * 64 + tid];
        atomicAdd(&g_outAcc[tid], p);
    }
    sigall(&g_tail);
    if (bid != 0) return;

    // ================= block 0: finalize + reset state for next replay =================
    waitge(&g_tail, (ep + 1u) * 4u);
    if (tid < 64) {
        float o = __ldg(b4b + tid) + g_outAcc[tid];  // plain load of atomic-written data
        out[tid] = o;
        g_outAcc[tid] = 0.f;
    }
    if (tid < 257) { d_binW[tid] = 0.f; d_binWE[tid] = 0.f; }
}

// ---------------- launch: ONE kernel, one graph node ----------------
extern "C" void kernel_launch(void* const* d_in, const int* in_sizes, int n_in,
                              void* d_out, int out_size) {
    const float* adj = (const float*)d_in[1];
    int P = in_sizes[1];
    kAll<<<NGRID, NTHR>>>(adj, P,
        (const float*)d_in[3],  (const float*)d_in[4],
        (const float*)d_in[5],  (const float*)d_in[6],
        (const float*)d_in[7],  (const float*)d_in[8],
        (const float*)d_in[9],  (const float*)d_in[10],
        (const float*)d_in[11], (const float*)d_in[12],
        (const float*)d_in[13], (const float*)d_in[14],
        (const float*)d_in[15], (const float*)d_in[16],
        (const float*)d_in[17], (const float*)d_in[18],
        (float*)d_out);
}